// round 10
// baseline (speedup 1.0000x reference)
#include <cuda_runtime.h>
#include <cuda_bf16.h>

// Problem constants (fixed for RoIPointPool3d_23845658427905)
#define Bn 4
#define Nn 16384
#define Mn 128
#define Cn 128
#define Sn 512
#define ROW (3 + Cn)          // 131 floats per pooled row
#define NWORDS (Nn / 32)      // 512 ballot words per box

// Kernel A1 tiling: each CTA = 512 points x 32 boxes
#define PCH 512               // points per chunk
#define NCHUNK (Nn / PCH)     // 32
#define BG 32                 // boxes per CTA
#define NBG (Mn / BG)         // 4

// Kernel A2 / select
#define NT 512
#define NWARP (NT / 32)

// Kernel B tiling
#define RT 8                  // row-tiles per box
#define RS (Sn / RT)          // 64 output rows per tile
#define NTB 256
#define NWARPB (NTB / 32)
#define TILE_F (RS * ROW)     // 8384 floats per tile (33536 B, 16B-aligned multiple)
#define TILE_V (TILE_F / 4)   // 2096 float4 per tile

// Scratch (device globals: allocation-free)
__device__ float    g_boxp[Bn * Mn * 8];          // cx,cy,cz,hx,hy,hz,cosa,sina
__device__ unsigned g_words[Bn * Mn * NWORDS];    // in-box bitmasks (1 MB)
__device__ int      g_table[Bn * Mn * Sn];        // per-box compacted indices
__device__ int      g_cnt[Bn * Mn];               // clamped counts

// ---------------- A0: per-box parameter precompute ----------------
__global__ void roipool_params_kernel(const float* __restrict__ boxes)
{
    const int bm = threadIdx.x;                   // 512 threads, one per box
    const float* box = boxes + bm * 7;
    const float dz = box[5];
    float* p = g_boxp + bm * 8;
    p[0] = box[0];                                          // cx
    p[1] = box[1];                                          // cy
    p[2] = __fadd_rn(box[2], __fmul_rn(0.5f, dz));          // cz (geometric center)
    p[3] = __fmul_rn(0.5f, box[3]);                         // hx
    p[4] = __fmul_rn(0.5f, box[4]);                         // hy
    p[5] = __fmul_rn(0.5f, dz);                             // hz
    const double nrz = -(double)box[6];
    p[6] = (float)cos(nrz);                                 // cosa
    p[7] = (float)sin(nrz);                                 // sina
}

// ---------------- A1: point-in-box tests, points loaded once per 32 boxes ----
__global__ __launch_bounds__(512, 3) void roipool_test_kernel(
    const float* __restrict__ points)             // (B, N, 3)
{
    __shared__ float s_p[BG * 8];                 // box params for this group
    __shared__ unsigned s_bw[BG * 16];            // ballot words: [box][warp]

    const int cta   = blockIdx.x;
    const int bg    = cta & (NBG - 1);
    const int chunk = (cta >> 2) & (NCHUNK - 1);
    const int b     = cta >> 7;                   // / (NBG*NCHUNK) = /128
    const int tid   = threadIdx.x;
    const int lane  = tid & 31;
    const int wid   = tid >> 5;

    const int box_base = b * Mn + bg * BG;
    if (tid < BG * 8) s_p[tid] = g_boxp[box_base * 8 + tid];

    const int i = chunk * PCH + tid;
    const float* pp = points + ((size_t)b * Nn + i) * 3;
    const float px = pp[0];
    const float py = pp[1];
    const float pz = pp[2];
    __syncthreads();

    #pragma unroll 4
    for (int m = 0; m < BG; m++) {
        const float cx = s_p[m * 8 + 0];
        const float cy = s_p[m * 8 + 1];
        const float cz = s_p[m * 8 + 2];
        const float hx = s_p[m * 8 + 3];
        const float hy = s_p[m * 8 + 4];
        const float hz = s_p[m * 8 + 5];
        const float cosa = s_p[m * 8 + 6];
        const float sina = s_p[m * 8 + 7];
        const float sx = __fsub_rn(px, cx);
        const float sy = __fsub_rn(py, cy);
        const float lx = __fsub_rn(__fmul_rn(sx, cosa), __fmul_rn(sy, sina));
        const float ly = __fadd_rn(__fmul_rn(sx, sina), __fmul_rn(sy, cosa));
        const bool in =
            (fabsf(__fsub_rn(pz, cz)) <= hz) &&
            (lx > -hx) && (lx < hx) &&
            (ly > -hy) && (ly < hy);
        const unsigned bal = __ballot_sync(0xffffffffu, in);
        if (lane == 0) s_bw[m * 16 + wid] = bal;
    }
    __syncthreads();

    const int m = tid >> 4;
    const int w = tid & 15;
    g_words[(size_t)(box_base + m) * NWORDS + chunk * 16 + w] = s_bw[tid];
}

// ---------------- A2: scan + ordered compaction ----------------
__global__ __launch_bounds__(NT, 3) void roipool_scan_kernel(
    float* __restrict__ out, int write_flags)
{
    __shared__ int s_warpSum[16];
    __shared__ int s_total;

    const int bm   = blockIdx.x;
    const int tid  = threadIdx.x;
    const int lane = tid & 31;
    const int wid  = tid >> 5;

    unsigned w = g_words[(size_t)bm * NWORDS + tid];   // NWORDS == NT
    const int c = __popc(w);
    int incl = c;
    #pragma unroll
    for (int off = 1; off < 32; off <<= 1) {
        int v = __shfl_up_sync(0xffffffffu, incl, off);
        if (lane >= off) incl += v;
    }
    if (lane == 31) s_warpSum[wid] = incl;
    __syncthreads();
    if (wid == 0) {
        int v = (lane < 16) ? s_warpSum[lane] : 0;
        int iv = v;
        #pragma unroll
        for (int off = 1; off < 16; off <<= 1) {
            int t = __shfl_up_sync(0xffffffffu, iv, off);
            if (lane >= off) iv += t;
        }
        if (lane < 16) s_warpSum[lane] = iv - v;
        if (lane == 15) s_total = iv;
    }
    __syncthreads();

    int base = s_warpSum[wid] + (incl - c);
    const int word_pt = tid * 32;
    int* tbl = g_table + (size_t)bm * Sn;
    while (w) {
        const int bit = __ffs(w) - 1;
        w &= (w - 1);
        if (base < Sn) tbl[base] = word_pt + bit;
        base++;
    }

    if (tid == 0) {
        int cnt = s_total;
        if (cnt > Sn) cnt = Sn;
        g_cnt[bm] = cnt;
        if (write_flags)
            out[(size_t)Bn * Mn * Sn * ROW + bm] = (cnt == 0) ? 1.0f : 0.0f;
    }
}

// ---------------- B: stage tile image in shared, flat float4 copy-out -------
__global__ __launch_bounds__(NTB) void roipool_write_kernel(
    const float* __restrict__ points,   // (B, N, 3)
    const float* __restrict__ feats,    // (B, N, C)
    float* __restrict__ out)            // (B, M, S, 131)
{
    __shared__ float s_tile[TILE_F];    // exact byte image of this 64-row tile

    const int bm   = blockIdx.x >> 3;       // / RT
    const int t    = blockIdx.x & (RT - 1);
    const int b    = bm >> 7;
    const int tid  = threadIdx.x;
    const int lane = tid & 31;
    const int wid  = tid >> 5;

    const int cnt = g_cnt[bm];
    const int r0 = t * RS;
    // tile base: 16B-aligned (r0*ROW*4 = t*33536)
    float4* otile = (float4*)(out + (size_t)bm * Sn * ROW + (size_t)r0 * ROW);

    if (cnt == 0) {
        const float4 z = make_float4(0.f, 0.f, 0.f, 0.f);
        #pragma unroll 4
        for (int e = tid; e < TILE_V; e += NTB) otile[e] = z;
        return;
    }

    const float* pts = points + (size_t)b * Nn * 3;
    const float4* fb4 = (const float4*)(feats + (size_t)b * Nn * Cn);
    const int* tbl    = g_table + (size_t)bm * Sn;

    // ---- stage: warp per staged row k (row r0+k uses source (r0+k) % cnt) ----
    for (int k = wid; k < RS; k += NWARPB) {
        const int idx = tbl[(r0 + k) % cnt];
        float* sw = s_tile + k * ROW;
        // 128 features in one LDG.128 per lane (feature rows are 512B-aligned)
        const float4 f = fb4[(size_t)idx * (Cn / 4) + lane];
        const int base = 3 + lane * 4;
        sw[base + 0] = f.x;
        sw[base + 1] = f.y;
        sw[base + 2] = f.z;
        sw[base + 3] = f.w;
        if (lane < 3) sw[lane] = pts[idx * 3 + lane];
    }
    __syncthreads();

    // ---- copy: flat, fully coalesced float4 shared -> global ----
    const float4* st4 = (const float4*)s_tile;
    #pragma unroll 4
    for (int e = tid; e < TILE_V; e += NTB) {
        otile[e] = st4[e];
    }
}

extern "C" void kernel_launch(void* const* d_in, const int* in_sizes, int n_in,
                              void* d_out, int out_size)
{
    const float* points = (const float*)d_in[0];   // (B, N, 3)
    const float* feats  = (const float*)d_in[1];   // (B, N, C)
    const float* boxes  = (const float*)d_in[2];   // (B, M, 7)
    float* out = (float*)d_out;

    const long long pooled = (long long)Bn * Mn * Sn * ROW;   // 34,340,864
    const int write_flags = ((long long)out_size >= pooled + (long long)Bn * Mn) ? 1 : 0;

    roipool_params_kernel<<<1, Bn * Mn>>>(boxes);
    roipool_test_kernel<<<Bn * NCHUNK * NBG, 512>>>(points);
    roipool_scan_kernel<<<Bn * Mn, NT>>>(out, write_flags);
    roipool_write_kernel<<<Bn * Mn * RT, NTB>>>(points, feats, out);
}

// round 11
// speedup vs baseline: 1.0879x; 1.0879x over previous
#include <cuda_runtime.h>
#include <cuda_bf16.h>
#include <cstdint>

// Problem constants (fixed for RoIPointPool3d_23845658427905)
#define Bn 4
#define Nn 16384
#define Mn 128
#define Cn 128
#define Sn 512
#define ROW (3 + Cn)          // 131 floats per pooled row
#define NWORDS (Nn / 32)      // 512 ballot words per box

// Kernel A1 tiling: each CTA = 512 points x 32 boxes
#define PCH 512               // points per chunk
#define NCHUNK (Nn / PCH)     // 32
#define BG 32                 // boxes per CTA
#define NBG (Mn / BG)         // 4

// Kernel A2 / select
#define NT 512
#define NWARP (NT / 32)

// Kernel B tiling
#define RT 8                  // row-tiles per box
#define RS (Sn / RT)          // 64 output rows per tile
#define NTB 256
#define NWARPB (NTB / 32)
#define TILE_F (RS * ROW)     // 8384 floats = 33536 B per tile (16B multiple)

// Scratch (device globals: allocation-free)
__device__ float    g_boxp[Bn * Mn * 8];          // cx,cy,cz,hx,hy,hz,cosa,sina
__device__ unsigned g_words[Bn * Mn * NWORDS];    // in-box bitmasks (1 MB)
__device__ int      g_table[Bn * Mn * Sn];        // per-box compacted indices
__device__ int      g_cnt[Bn * Mn];               // clamped counts

// ---------------- A0: per-box parameter precompute ----------------
__global__ void roipool_params_kernel(const float* __restrict__ boxes)
{
    const int bm = threadIdx.x;                   // 512 threads, one per box
    const float* box = boxes + bm * 7;
    const float dz = box[5];
    float* p = g_boxp + bm * 8;
    p[0] = box[0];                                          // cx
    p[1] = box[1];                                          // cy
    p[2] = __fadd_rn(box[2], __fmul_rn(0.5f, dz));          // cz (geometric center)
    p[3] = __fmul_rn(0.5f, box[3]);                         // hx
    p[4] = __fmul_rn(0.5f, box[4]);                         // hy
    p[5] = __fmul_rn(0.5f, dz);                             // hz
    const double nrz = -(double)box[6];
    p[6] = (float)cos(nrz);                                 // cosa
    p[7] = (float)sin(nrz);                                 // sina
}

// ---------------- A1: point-in-box tests, points loaded once per 32 boxes ----
__global__ __launch_bounds__(512, 3) void roipool_test_kernel(
    const float* __restrict__ points)             // (B, N, 3)
{
    __shared__ float s_p[BG * 8];                 // box params for this group
    __shared__ unsigned s_bw[BG * 16];            // ballot words: [box][warp]

    const int cta   = blockIdx.x;
    const int bg    = cta & (NBG - 1);
    const int chunk = (cta >> 2) & (NCHUNK - 1);
    const int b     = cta >> 7;                   // / (NBG*NCHUNK) = /128
    const int tid   = threadIdx.x;
    const int lane  = tid & 31;
    const int wid   = tid >> 5;

    const int box_base = b * Mn + bg * BG;
    if (tid < BG * 8) s_p[tid] = g_boxp[box_base * 8 + tid];

    const int i = chunk * PCH + tid;
    const float* pp = points + ((size_t)b * Nn + i) * 3;
    const float px = pp[0];
    const float py = pp[1];
    const float pz = pp[2];
    __syncthreads();

    #pragma unroll 4
    for (int m = 0; m < BG; m++) {
        const float cx = s_p[m * 8 + 0];
        const float cy = s_p[m * 8 + 1];
        const float cz = s_p[m * 8 + 2];
        const float hx = s_p[m * 8 + 3];
        const float hy = s_p[m * 8 + 4];
        const float hz = s_p[m * 8 + 5];
        const float cosa = s_p[m * 8 + 6];
        const float sina = s_p[m * 8 + 7];
        const float sx = __fsub_rn(px, cx);
        const float sy = __fsub_rn(py, cy);
        const float lx = __fsub_rn(__fmul_rn(sx, cosa), __fmul_rn(sy, sina));
        const float ly = __fadd_rn(__fmul_rn(sx, sina), __fmul_rn(sy, cosa));
        const bool in =
            (fabsf(__fsub_rn(pz, cz)) <= hz) &&
            (lx > -hx) && (lx < hx) &&
            (ly > -hy) && (ly < hy);
        const unsigned bal = __ballot_sync(0xffffffffu, in);
        if (lane == 0) s_bw[m * 16 + wid] = bal;
    }
    __syncthreads();

    const int m = tid >> 4;
    const int w = tid & 15;
    g_words[(size_t)(box_base + m) * NWORDS + chunk * 16 + w] = s_bw[tid];
}

// ---------------- A2: scan + ordered compaction ----------------
__global__ __launch_bounds__(NT, 3) void roipool_scan_kernel(
    float* __restrict__ out, int write_flags)
{
    __shared__ int s_warpSum[16];
    __shared__ int s_total;

    const int bm   = blockIdx.x;
    const int tid  = threadIdx.x;
    const int lane = tid & 31;
    const int wid  = tid >> 5;

    unsigned w = g_words[(size_t)bm * NWORDS + tid];   // NWORDS == NT
    const int c = __popc(w);
    int incl = c;
    #pragma unroll
    for (int off = 1; off < 32; off <<= 1) {
        int v = __shfl_up_sync(0xffffffffu, incl, off);
        if (lane >= off) incl += v;
    }
    if (lane == 31) s_warpSum[wid] = incl;
    __syncthreads();
    if (wid == 0) {
        int v = (lane < 16) ? s_warpSum[lane] : 0;
        int iv = v;
        #pragma unroll
        for (int off = 1; off < 16; off <<= 1) {
            int t = __shfl_up_sync(0xffffffffu, iv, off);
            if (lane >= off) iv += t;
        }
        if (lane < 16) s_warpSum[lane] = iv - v;
        if (lane == 15) s_total = iv;
    }
    __syncthreads();

    int base = s_warpSum[wid] + (incl - c);
    const int word_pt = tid * 32;
    int* tbl = g_table + (size_t)bm * Sn;
    while (w) {
        const int bit = __ffs(w) - 1;
        w &= (w - 1);
        if (base < Sn) tbl[base] = word_pt + bit;
        base++;
    }

    if (tid == 0) {
        int cnt = s_total;
        if (cnt > Sn) cnt = Sn;
        g_cnt[bm] = cnt;
        if (write_flags)
            out[(size_t)Bn * Mn * Sn * ROW + bm] = (cnt == 0) ? 1.0f : 0.0f;
    }
}

// ---------------- B: stage tile via STS, drain via cp.async.bulk (TMA) ------
__global__ __launch_bounds__(NTB) void roipool_write_kernel(
    const float* __restrict__ points,   // (B, N, 3)
    const float* __restrict__ feats,    // (B, N, C)
    float* __restrict__ out)            // (B, M, S, 131)
{
    __shared__ __align__(16) float s_tile[TILE_F];   // exact image of this 64-row tile

    const int bm   = blockIdx.x >> 3;       // / RT
    const int t    = blockIdx.x & (RT - 1);
    const int b    = bm >> 7;
    const int tid  = threadIdx.x;
    const int lane = tid & 31;
    const int wid  = tid >> 5;

    const int cnt = g_cnt[bm];
    const int r0 = t * RS;
    float* otile = out + (size_t)bm * Sn * ROW + (size_t)r0 * ROW;  // 16B aligned

    if (cnt == 0) {
        const float4 z = make_float4(0.f, 0.f, 0.f, 0.f);
        float4* st4 = (float4*)s_tile;
        #pragma unroll 4
        for (int e = tid; e < TILE_F / 4; e += NTB) st4[e] = z;
    } else {
        const float* pts = points + (size_t)b * Nn * 3;
        const float* fb  = feats  + (size_t)b * Nn * Cn;
        const int* tbl   = g_table + (size_t)bm * Sn;

        // source-major staging: load each needed source row once into registers,
        // STS it to every replica slot in this tile (contiguous 128B warp stores,
        // conflict-free at any 4B alignment)
        for (int j = wid; j < cnt; j += NWARPB) {
            int r = (j >= r0) ? j : j + ((r0 - j + cnt - 1) / cnt) * cnt;
            if (r >= r0 + RS) continue;

            const int idx = tbl[j];
            const float* fr = fb + (size_t)idx * Cn;
            const float v0 = (lane < 3) ? pts[idx * 3 + lane] : fr[lane - 3];
            const float v1 = fr[32 + lane - 3];
            const float v2 = fr[64 + lane - 3];
            const float v3 = fr[96 + lane - 3];
            const float v4 = (lane < 3) ? fr[125 + lane] : 0.0f;

            for (; r < r0 + RS; r += cnt) {
                float* sw = s_tile + (r - r0) * ROW;
                sw[lane]       = v0;
                sw[32 + lane]  = v1;
                sw[64 + lane]  = v2;
                sw[96 + lane]  = v3;
                if (lane < 3) sw[128 + lane] = v4;
            }
        }
    }
    __syncthreads();

    // one thread drains the tile via the async (TMA) proxy — no STG issue cost
    if (tid == 0) {
        uint32_t saddr;
        asm("{ .reg .u64 tmp; cvta.to.shared.u64 tmp, %1; cvt.u32.u64 %0, tmp; }"
            : "=r"(saddr) : "l"((const void*)s_tile));
        asm volatile("fence.proxy.async.shared::cta;" ::: "memory");
        asm volatile(
            "cp.async.bulk.global.shared::cta.bulk_group [%0], [%1], %2;"
            :: "l"(otile), "r"(saddr), "r"((uint32_t)(TILE_F * 4))
            : "memory");
        asm volatile("cp.async.bulk.commit_group;" ::: "memory");
        // wait for the bulk engine to finish READING shared before CTA teardown
        asm volatile("cp.async.bulk.wait_group.read 0;" ::: "memory");
    }
}

extern "C" void kernel_launch(void* const* d_in, const int* in_sizes, int n_in,
                              void* d_out, int out_size)
{
    const float* points = (const float*)d_in[0];   // (B, N, 3)
    const float* feats  = (const float*)d_in[1];   // (B, N, C)
    const float* boxes  = (const float*)d_in[2];   // (B, M, 7)
    float* out = (float*)d_out;

    const long long pooled = (long long)Bn * Mn * Sn * ROW;   // 34,340,864
    const int write_flags = ((long long)out_size >= pooled + (long long)Bn * Mn) ? 1 : 0;

    roipool_params_kernel<<<1, Bn * Mn>>>(boxes);
    roipool_test_kernel<<<Bn * NCHUNK * NBG, 512>>>(points);
    roipool_scan_kernel<<<Bn * Mn, NT>>>(out, write_flags);
    roipool_write_kernel<<<Bn * Mn * RT, NTB>>>(points, feats, out);
}

// round 12
// speedup vs baseline: 1.3665x; 1.2560x over previous
#include <cuda_runtime.h>
#include <cuda_bf16.h>
#include <cstdint>

// Problem constants (fixed for RoIPointPool3d_23845658427905)
#define Bn 4
#define Nn 16384
#define Mn 128
#define Cn 128
#define Sn 512
#define ROW (3 + Cn)          // 131 floats per pooled row
#define NWORDS (Nn / 32)      // 512 ballot words per box

// Kernel A1 tiling: each CTA = 512 points x 32 boxes
#define PCH 512               // points per chunk
#define NCHUNK (Nn / PCH)     // 32
#define BG 32                 // boxes per CTA
#define NBG (Mn / BG)         // 4

// Kernel B tiling
#define RT 8                  // row-tiles per box
#define RS (Sn / RT)          // 64 output rows per tile
#define NTB 256
#define NWARPB (NTB / 32)     // 8

// Scratch (device globals: allocation-free)
__device__ float    g_boxp[Bn * Mn * 8];          // cx,cy,cz,hx,hy,hz,cosa,sina
__device__ unsigned g_words[Bn * Mn * NWORDS];    // in-box bitmasks (1 MB)

// ---------------- A0: per-box parameter precompute ----------------
__global__ void roipool_params_kernel(const float* __restrict__ boxes)
{
    const int bm = threadIdx.x;                   // 512 threads, one per box
    const float* box = boxes + bm * 7;
    const float dz = box[5];
    float* p = g_boxp + bm * 8;
    p[0] = box[0];                                          // cx
    p[1] = box[1];                                          // cy
    p[2] = __fadd_rn(box[2], __fmul_rn(0.5f, dz));          // cz (geometric center)
    p[3] = __fmul_rn(0.5f, box[3]);                         // hx
    p[4] = __fmul_rn(0.5f, box[4]);                         // hy
    p[5] = __fmul_rn(0.5f, dz);                             // hz
    const double nrz = -(double)box[6];
    p[6] = (float)cos(nrz);                                 // cosa
    p[7] = (float)sin(nrz);                                 // sina
}

// ---------------- A1: point-in-box tests, points loaded once per 32 boxes ----
__global__ __launch_bounds__(512, 3) void roipool_test_kernel(
    const float* __restrict__ points)             // (B, N, 3)
{
    __shared__ float s_p[BG * 8];                 // box params for this group
    __shared__ unsigned s_bw[BG * 16];            // ballot words: [box][warp]

    const int cta   = blockIdx.x;
    const int bg    = cta & (NBG - 1);
    const int chunk = (cta >> 2) & (NCHUNK - 1);
    const int b     = cta >> 7;                   // / (NBG*NCHUNK) = /128
    const int tid   = threadIdx.x;
    const int lane  = tid & 31;
    const int wid   = tid >> 5;

    const int box_base = b * Mn + bg * BG;
    if (tid < BG * 8) s_p[tid] = g_boxp[box_base * 8 + tid];

    const int i = chunk * PCH + tid;
    const float* pp = points + ((size_t)b * Nn + i) * 3;
    const float px = pp[0];
    const float py = pp[1];
    const float pz = pp[2];
    __syncthreads();

    #pragma unroll 4
    for (int m = 0; m < BG; m++) {
        const float cx = s_p[m * 8 + 0];
        const float cy = s_p[m * 8 + 1];
        const float cz = s_p[m * 8 + 2];
        const float hx = s_p[m * 8 + 3];
        const float hy = s_p[m * 8 + 4];
        const float hz = s_p[m * 8 + 5];
        const float cosa = s_p[m * 8 + 6];
        const float sina = s_p[m * 8 + 7];
        const float sx = __fsub_rn(px, cx);
        const float sy = __fsub_rn(py, cy);
        const float lx = __fsub_rn(__fmul_rn(sx, cosa), __fmul_rn(sy, sina));
        const float ly = __fadd_rn(__fmul_rn(sx, sina), __fmul_rn(sy, cosa));
        const bool in =
            (fabsf(__fsub_rn(pz, cz)) <= hz) &&
            (lx > -hx) && (lx < hx) &&
            (ly > -hy) && (ly < hy);
        const unsigned bal = __ballot_sync(0xffffffffu, in);
        if (lane == 0) s_bw[m * 16 + wid] = bal;
    }
    __syncthreads();

    const int m = tid >> 4;
    const int w = tid & 15;
    g_words[(size_t)(box_base + m) * NWORDS + chunk * 16 + w] = s_bw[tid];
}

// ---------------- B: in-CTA scan + compaction, then source-major tile write --
__global__ __launch_bounds__(NTB, 8) void roipool_write_kernel(
    const float* __restrict__ points,   // (B, N, 3)
    const float* __restrict__ feats,    // (B, N, C)
    float* __restrict__ out,            // (B, M, S, 131) [+ flags]
    int write_flags)
{
    __shared__ int s_table[Sn];         // compacted in-box point indices
    __shared__ int s_warpSum[NWARPB];
    __shared__ int s_total;

    const int bm   = blockIdx.x >> 3;       // / RT
    const int t    = blockIdx.x & (RT - 1);
    const int b    = bm >> 7;
    const int tid  = threadIdx.x;
    const int lane = tid & 31;
    const int wid  = tid >> 5;

    // ---- local scan + compaction of this box's 2KB bitmask (L2-hot) ----
    // thread tid owns words 2*tid and 2*tid+1 (points [64*tid, 64*tid+64))
    const uint2 ww = ((const uint2*)(g_words + (size_t)bm * NWORDS))[tid];
    const int c0 = __popc(ww.x);
    const int c1 = __popc(ww.y);
    const int c  = c0 + c1;
    int incl = c;
    #pragma unroll
    for (int off = 1; off < 32; off <<= 1) {
        int v = __shfl_up_sync(0xffffffffu, incl, off);
        if (lane >= off) incl += v;
    }
    if (lane == 31) s_warpSum[wid] = incl;
    __syncthreads();
    if (wid == 0) {
        int v = (lane < NWARPB) ? s_warpSum[lane] : 0;
        int iv = v;
        #pragma unroll
        for (int off = 1; off < NWARPB; off <<= 1) {
            int tmp = __shfl_up_sync(0xffffffffu, iv, off);
            if (lane >= off) iv += tmp;
        }
        if (lane < NWARPB) s_warpSum[lane] = iv - v;   // exclusive warp bases
        if (lane == NWARPB - 1) s_total = iv;
    }
    __syncthreads();

    {
        int base = s_warpSum[wid] + (incl - c);
        unsigned w0 = ww.x;
        const int pt0 = tid * 64;
        while (w0) {
            const int bit = __ffs(w0) - 1;
            w0 &= (w0 - 1);
            if (base < Sn) s_table[base] = pt0 + bit;
            base++;
        }
        unsigned w1 = ww.y;
        int base1 = s_warpSum[wid] + (incl - c) + c0;
        const int pt1 = tid * 64 + 32;
        while (w1) {
            const int bit = __ffs(w1) - 1;
            w1 &= (w1 - 1);
            if (base1 < Sn) s_table[base1] = pt1 + bit;
            base1++;
        }
    }
    __syncthreads();

    int cnt = s_total;
    if (cnt > Sn) cnt = Sn;

    const int r0 = t * RS;
    const int r1 = r0 + RS;
    float* outbox = out + (size_t)bm * Sn * ROW;

    if (write_flags && t == 0 && tid == 0)
        out[(size_t)Bn * Mn * Sn * ROW + bm] = (cnt == 0) ? 1.0f : 0.0f;

    if (cnt == 0) {
        for (int r = r0 + wid; r < r1; r += NWARPB) {
            float* orow = outbox + (size_t)r * ROW;
            __stcs(&orow[lane], 0.f);
            __stcs(&orow[32 + lane], 0.f);
            __stcs(&orow[64 + lane], 0.f);
            __stcs(&orow[96 + lane], 0.f);
            if (lane < 3) __stcs(&orow[128 + lane], 0.f);
        }
        return;
    }

    const float* pts = points + (size_t)b * Nn * 3;
    const float* fb  = feats  + (size_t)b * Nn * Cn;

    // source-major within the tile: output row r takes source (r % cnt)
    for (int j = wid; j < cnt; j += NWARPB) {
        int r = (j >= r0) ? j : j + ((r0 - j + cnt - 1) / cnt) * cnt;
        if (r >= r1) continue;

        const int idx = s_table[j];
        const float* fr = fb + (size_t)idx * Cn;
        const float v0 = (lane < 3) ? pts[idx * 3 + lane] : fr[lane - 3];
        const float v1 = fr[32 + lane - 3];
        const float v2 = fr[64 + lane - 3];
        const float v3 = fr[96 + lane - 3];
        const float v4 = (lane < 3) ? fr[125 + lane] : 0.0f;

        for (; r < r1; r += cnt) {
            float* orow = outbox + (size_t)r * ROW;
            __stcs(&orow[lane], v0);
            __stcs(&orow[32 + lane], v1);
            __stcs(&orow[64 + lane], v2);
            __stcs(&orow[96 + lane], v3);
            if (lane < 3) __stcs(&orow[128 + lane], v4);
        }
    }
}

extern "C" void kernel_launch(void* const* d_in, const int* in_sizes, int n_in,
                              void* d_out, int out_size)
{
    const float* points = (const float*)d_in[0];   // (B, N, 3)
    const float* feats  = (const float*)d_in[1];   // (B, N, C)
    const float* boxes  = (const float*)d_in[2];   // (B, M, 7)
    float* out = (float*)d_out;

    const long long pooled = (long long)Bn * Mn * Sn * ROW;   // 34,340,864
    const int write_flags = ((long long)out_size >= pooled + (long long)Bn * Mn) ? 1 : 0;

    roipool_params_kernel<<<1, Bn * Mn>>>(boxes);
    roipool_test_kernel<<<Bn * NCHUNK * NBG, 512>>>(points);
    roipool_write_kernel<<<Bn * Mn * RT, NTB>>>(points, feats, out, write_flags);
}